// round 13
// baseline (speedup 1.0000x reference)
#include <cuda_runtime.h>
#include <math.h>

#define C_CH 64
#define NPTS 500000
#define NC (NPTS * C_CH)          // 32,000,000
#define NC4 (NC / 4)              // 8,000,000 float4s
#define NC8 (NC4 / 2)             // 4,000,000  (ILP-2 split; NC8 % 16 == 0)

#define THREADS 640               // 20 warps; 640 % 16 == 0
#define BLOCKS  (NC8 / THREADS)   // 6250 exactly

// ---------------- helpers ----------------
__device__ __forceinline__ float softplus_fast(float m)
{
    return (m > 15.f) ? m : __logf(1.f + __expf(m));
}

__device__ __forceinline__ float sig_diff_clamp(float u, float l)
{
    // sign = -sign(l+u); likelihood = |sigmoid(s*u) - sigmoid(s*l)|, clamped.
    float t = u + l;
    float s = (t > 0.f) ? -1.f : ((t < 0.f) ? 1.f : 0.f);
    float ea = __expf(s * u);
    float eb = __expf(s * l);
    float d = __fdividef(ea - eb, (1.f + ea) * (1.f + eb));
    return fmaxf(fabsf(d), 1e-9f);
}

// general-path chain (shared-memory params); rare path, spills are OK
__device__ __forceinline__ float chain_shared(
    float x, int c,
    const float* sp0, const float* bv0, const float* tf0,
    const float* sp1, const float* bv1, const float* tf1,
    const float* sp2, const float* bv2, const float* tf2,
    const float* sp3, const float* bv3, const float* tf3)
{
    float h[3], h2[3];
    #pragma unroll
    for (int j = 0; j < 3; j++) {
        float v = fmaf(sp0[c * 3 + j], x, bv0[c * 3 + j]);
        h[j] = v + tf0[c * 3 + j] * tanhf(v);
    }
    #pragma unroll
    for (int i = 0; i < 3; i++) {
        float v = bv1[c * 3 + i];
        #pragma unroll
        for (int j = 0; j < 3; j++) v = fmaf(sp1[c * 9 + i * 3 + j], h[j], v);
        h2[i] = v + tf1[c * 3 + i] * tanhf(v);
    }
    #pragma unroll
    for (int i = 0; i < 3; i++) {
        float v = bv2[c * 3 + i];
        #pragma unroll
        for (int j = 0; j < 3; j++) v = fmaf(sp2[c * 9 + i * 3 + j], h2[j], v);
        h[i] = v + tf2[c * 3 + i] * tanhf(v);
    }
    float v = bv3[c];
    #pragma unroll
    for (int j = 0; j < 3; j++) v = fmaf(sp3[c * 3 + j], h[j], v);
    return v + tf3[c] * tanhf(v);
}

// ---------------- single kernel, 640-thread blocks, register-capped --------
__global__ void __launch_bounds__(THREADS, 3)
eb_all(const float4* __restrict__ in, const float4* __restrict__ noise,
       float4* __restrict__ out_o, float4* __restrict__ out_l, int write_outputs,
       const float* __restrict__ m0, const float* __restrict__ b0, const float* __restrict__ f0,
       const float* __restrict__ m1, const float* __restrict__ b1, const float* __restrict__ f1,
       const float* __restrict__ m2, const float* __restrict__ b2, const float* __restrict__ f2,
       const float* __restrict__ m3, const float* __restrict__ b3, const float* __restrict__ f3)
{
    __shared__ float4 s_A4[16];
    __shared__ float4 s_Bu4[16];
    // general-path params (touched only when some f != 0)
    __shared__ float s_sp0[192], s_b0[192], s_tf0[192];
    __shared__ float s_sp1[576], s_b1[192], s_tf1[192];
    __shared__ float s_sp2[576], s_b2[192], s_tf2[192];
    __shared__ float s_sp3[192], s_b3[64],  s_tf3[64];

    int t = threadIdx.x;
    int i = blockIdx.x * THREADS + t;     // grid exactly covers NC8
    int j = i + NC8;                      // NC8 % 16 == 0 -> same channel-group
    int cg = i & 15;

    // ---- f-zero check (640 values over 640 threads; L2-hot after wave 1) ----
    bool fzl = true;
    {
        float f;
        if (t < 192)       f = f0[t];
        else if (t < 384)  f = f1[t - 192];
        else if (t < 576)  f = f2[t - 384];
        else               f = f3[t - 576];
        if (f != 0.f) fzl = false;
    }
    int fast = __syncthreads_and(fzl ? 1 : 0);

    if (fast) {
        // per-block affine compose: 64 threads, params L2-hot
        if (t < C_CH) {
            int c = t;
            float a0[3], bb[3];
            #pragma unroll
            for (int jj = 0; jj < 3; jj++) {
                a0[jj] = softplus_fast(m0[c * 3 + jj]);
                bb[jj] = b0[c * 3 + jj];
            }
            float a1[3], bv1[3];
            #pragma unroll
            for (int ii = 0; ii < 3; ii++) {
                float sp, av = 0.f, bv = b1[c * 3 + ii];
                #pragma unroll
                for (int jj = 0; jj < 3; jj++) {
                    sp = softplus_fast(m1[c * 9 + ii * 3 + jj]);
                    av = fmaf(sp, a0[jj], av);
                    bv = fmaf(sp, bb[jj], bv);
                }
                a1[ii] = av; bv1[ii] = bv;
            }
            float a2[3], bv2[3];
            #pragma unroll
            for (int ii = 0; ii < 3; ii++) {
                float sp, av = 0.f, bv = b2[c * 3 + ii];
                #pragma unroll
                for (int jj = 0; jj < 3; jj++) {
                    sp = softplus_fast(m2[c * 9 + ii * 3 + jj]);
                    av = fmaf(sp, a1[jj], av);
                    bv = fmaf(sp, bv1[jj], bv);
                }
                a2[ii] = av; bv2[ii] = bv;
            }
            float A = 0.f, B = b3[c];
            #pragma unroll
            for (int jj = 0; jj < 3; jj++) {
                float sp = softplus_fast(m3[c * 3 + jj]);
                A = fmaf(sp, a2[jj], A);
                B = fmaf(sp, bv2[jj], B);
            }
            ((float*)s_A4)[c]  = A;
            ((float*)s_Bu4)[c] = B + 0.5f * A;
        }
        __syncthreads();

        // ---- streaming section: proven hot-loop shape ----
        float4 A  = s_A4[cg];
        float4 Bu = s_Bu4[cg];

        float4 xa = in[i];
        float4 na = noise[i];
        float4 xb = in[j];
        float4 nb = noise[j];
        xa.x += na.x; xa.y += na.y; xa.z += na.z; xa.w += na.w;
        xb.x += nb.x; xb.y += nb.y; xb.z += nb.z; xb.w += nb.w;
        if (write_outputs) { out_o[i] = xa; out_o[j] = xb; }

        float ua_x = fmaf(A.x, xa.x, Bu.x);
        float ua_y = fmaf(A.y, xa.y, Bu.y);
        float ua_z = fmaf(A.z, xa.z, Bu.z);
        float ua_w = fmaf(A.w, xa.w, Bu.w);
        float ub_x = fmaf(A.x, xb.x, Bu.x);
        float ub_y = fmaf(A.y, xb.y, Bu.y);
        float ub_z = fmaf(A.z, xb.z, Bu.z);
        float ub_w = fmaf(A.w, xb.w, Bu.w);

        float4 la, lb;
        la.x = sig_diff_clamp(ua_x, ua_x - A.x);
        la.y = sig_diff_clamp(ua_y, ua_y - A.y);
        la.z = sig_diff_clamp(ua_z, ua_z - A.z);
        la.w = sig_diff_clamp(ua_w, ua_w - A.w);
        lb.x = sig_diff_clamp(ub_x, ub_x - A.x);
        lb.y = sig_diff_clamp(ub_y, ub_y - A.y);
        lb.z = sig_diff_clamp(ub_z, ub_z - A.z);
        lb.w = sig_diff_clamp(ub_w, ub_w - A.w);

        out_l[i] = la;
        out_l[j] = lb;
    } else {
        // ---- general path (rare): params to shared, gated chain, spills OK --
        for (int idx = t; idx < 1536; idx += THREADS) {
            if (idx < 192)        s_sp0[idx]        = log1pf(expf(m0[idx]));
            else if (idx < 768)   s_sp1[idx - 192]  = log1pf(expf(m1[idx - 192]));
            else if (idx < 1344)  s_sp2[idx - 768]  = log1pf(expf(m2[idx - 768]));
            else                  s_sp3[idx - 1344] = log1pf(expf(m3[idx - 1344]));
        }
        for (int idx = t; idx < 640; idx += THREADS) {
            if (idx < 192)       s_tf0[idx]       = tanhf(f0[idx]);
            else if (idx < 384)  s_tf1[idx - 192] = tanhf(f1[idx - 192]);
            else if (idx < 576)  s_tf2[idx - 384] = tanhf(f2[idx - 384]);
            else                 s_tf3[idx - 576] = tanhf(f3[idx - 576]);
        }
        for (int idx = t; idx < 192; idx += THREADS) {
            s_b0[idx] = b0[idx];
            s_b1[idx] = b1[idx];
            s_b2[idx] = b2[idx];
        }
        if (t < 64) s_b3[t] = b3[t];
        __syncthreads();

        int c0 = cg * 4;
        #pragma unroll
        for (int half = 0; half < 2; half++) {
            int idx = half ? j : i;
            float4 x4 = in[idx];
            float4 n4 = noise[idx];
            x4.x += n4.x; x4.y += n4.y; x4.z += n4.z; x4.w += n4.w;
            if (write_outputs) out_o[idx] = x4;

            float vx[4] = {x4.x, x4.y, x4.z, x4.w};
            float lo[4];
            #pragma unroll
            for (int k = 0; k < 4; k++) {
                float u = chain_shared(vx[k] + 0.5f, c0 + k,
                                       s_sp0, s_b0, s_tf0, s_sp1, s_b1, s_tf1,
                                       s_sp2, s_b2, s_tf2, s_sp3, s_b3, s_tf3);
                float l = chain_shared(vx[k] - 0.5f, c0 + k,
                                       s_sp0, s_b0, s_tf0, s_sp1, s_b1, s_tf1,
                                       s_sp2, s_b2, s_tf2, s_sp3, s_b3, s_tf3);
                lo[k] = sig_diff_clamp(u, l);
            }
            float4 lk;
            lk.x = lo[0]; lk.y = lo[1]; lk.z = lo[2]; lk.w = lo[3];
            out_l[idx] = lk;
        }
    }
}

// ---------------- launch ----------------
extern "C" void kernel_launch(void* const* d_in, const int* in_sizes, int n_in,
                              void* d_out, int out_size)
{
    const float* inputs = (const float*)d_in[0];
    const float* noise  = (const float*)d_in[1];
    const float* m0 = (const float*)d_in[2];
    const float* b0 = (const float*)d_in[3];
    const float* f0 = (const float*)d_in[4];
    const float* m1 = (const float*)d_in[5];
    const float* b1 = (const float*)d_in[6];
    const float* f1 = (const float*)d_in[7];
    const float* m2 = (const float*)d_in[8];
    const float* b2 = (const float*)d_in[9];
    const float* f2 = (const float*)d_in[10];
    const float* m3 = (const float*)d_in[11];
    const float* b3 = (const float*)d_in[12];
    const float* f3 = (const float*)d_in[13];

    float* out = (float*)d_out;
    float* out_outputs;
    float* out_lik;
    int write_outputs;
    if (out_size >= 2 * NC) {
        out_outputs = out;          // (N, C) outputs first
        out_lik     = out + NC;     // then (N, C) likelihood
        write_outputs = 1;
    } else {
        out_outputs = out;
        out_lik     = out;
        write_outputs = 0;
    }

    eb_all<<<BLOCKS, THREADS>>>((const float4*)inputs, (const float4*)noise,
                                (float4*)out_outputs, (float4*)out_lik, write_outputs,
                                m0, b0, f0, m1, b1, f1, m2, b2, f2, m3, b3, f3);
}

// round 14
// speedup vs baseline: 1.2403x; 1.2403x over previous
#include <cuda_runtime.h>
#include <math.h>

#define C_CH 64
#define NPTS 500000
#define NC (NPTS * C_CH)          // 32,000,000
#define NC4 (NC / 4)              // 8,000,000 float4s
#define NC8 (NC4 / 2)             // 4,000,000  (ILP-2 split; NC8 % 16 == 0)
// NC8 == 15625 * 256 exactly -> no tail check needed

// ---------------- helpers ----------------
__device__ __forceinline__ float softplus_fast(float m)
{
    return (m > 15.f) ? m : __logf(1.f + __expf(m));
}

__device__ __forceinline__ float sig_diff_clamp(float u, float l)
{
    // sign = -sign(l+u); likelihood = |sigmoid(s*u) - sigmoid(s*l)|, clamped.
    float t = u + l;
    float s = (t > 0.f) ? -1.f : ((t < 0.f) ? 1.f : 0.f);
    float ea = __expf(s * u);
    float eb = __expf(s * l);
    float d = __fdividef(ea - eb, (1.f + ea) * (1.f + eb));
    return fmaxf(fabsf(d), 1e-9f);
}

// general-path chain (shared-memory params); rare path, spills are OK
__device__ __forceinline__ float chain_shared(
    float x, int c,
    const float* sp0, const float* bv0, const float* tf0,
    const float* sp1, const float* bv1, const float* tf1,
    const float* sp2, const float* bv2, const float* tf2,
    const float* sp3, const float* bv3, const float* tf3)
{
    float h[3], h2[3];
    #pragma unroll
    for (int j = 0; j < 3; j++) {
        float v = fmaf(sp0[c * 3 + j], x, bv0[c * 3 + j]);
        h[j] = v + tf0[c * 3 + j] * tanhf(v);
    }
    #pragma unroll
    for (int i = 0; i < 3; i++) {
        float v = bv1[c * 3 + i];
        #pragma unroll
        for (int j = 0; j < 3; j++) v = fmaf(sp1[c * 9 + i * 3 + j], h[j], v);
        h2[i] = v + tf1[c * 3 + i] * tanhf(v);
    }
    #pragma unroll
    for (int i = 0; i < 3; i++) {
        float v = bv2[c * 3 + i];
        #pragma unroll
        for (int j = 0; j < 3; j++) v = fmaf(sp2[c * 9 + i * 3 + j], h2[j], v);
        h[i] = v + tf2[c * 3 + i] * tanhf(v);
    }
    float v = bv3[c];
    #pragma unroll
    for (int j = 0; j < 3; j++) v = fmaf(sp3[c * 3 + j], h[j], v);
    return v + tf3[c] * tanhf(v);
}

// ---------------- single kernel, 256x8, cheap closed-form prologue ---------
__global__ void __launch_bounds__(256, 8)
eb_all(const float4* __restrict__ in, const float4* __restrict__ noise,
       float4* __restrict__ out_o, float4* __restrict__ out_l, int write_outputs,
       const float* __restrict__ m0, const float* __restrict__ b0, const float* __restrict__ f0,
       const float* __restrict__ m1, const float* __restrict__ b1, const float* __restrict__ f1,
       const float* __restrict__ m2, const float* __restrict__ b2, const float* __restrict__ f2,
       const float* __restrict__ m3, const float* __restrict__ b3, const float* __restrict__ f3)
{
    __shared__ float4 s_A4[16];
    __shared__ float4 s_Bu4[16];
    // non-uniform / general params (touched only off the closed-form path)
    __shared__ float s_sp0[192], s_b0[192], s_tf0[192];
    __shared__ float s_sp1[576], s_b1[192], s_tf1[192];
    __shared__ float s_sp2[576], s_b2[192], s_tf2[192];
    __shared__ float s_sp3[192], s_b3[64],  s_tf3[64];

    int t = threadIdx.x;
    int i = blockIdx.x * 256 + t;         // grid exactly covers NC8
    int j = i + NC8;                      // NC8 % 16 == 0 -> same channel-group
    int cg = i & 15;

    // ---- checks: all f == 0? each m-layer constant? (pure loads+compares) ----
    bool fzl = true;
    #pragma unroll
    for (int k = 0; k < 3; k++) {
        int idx = t + k * 256;
        if (idx < 640) {
            float f;
            if (idx < 192)       f = f0[idx];
            else if (idx < 384)  f = f1[idx - 192];
            else if (idx < 576)  f = f2[idx - 384];
            else                 f = f3[idx - 576];
            if (f != 0.f) fzl = false;
        }
    }
    float m0s = m0[0], m1s = m1[0], m2s = m2[0], m3s = m3[0];
    bool mul = true;
    #pragma unroll
    for (int k = 0; k < 6; k++) {
        int idx = t + k * 256;            // 1536 values over 256 threads
        float mv, ms;
        if (idx < 192)        { mv = m0[idx];        ms = m0s; }
        else if (idx < 768)   { mv = m1[idx - 192];  ms = m1s; }
        else if (idx < 1344)  { mv = m2[idx - 768];  ms = m2s; }
        else                  { mv = m3[idx - 1344]; ms = m3s; }
        if (mv != ms) mul = false;
    }
    int fast = __syncthreads_and(fzl ? 1 : 0);
    int muni = __syncthreads_and(mul ? 1 : 0);

    if (fast) {
        if (muni) {
            // ---- closed-form compose (uniform weights): 4 softplus only ----
            if (t < C_CH) {
                int c = t;
                float w0 = softplus_fast(m0s);
                float w1 = softplus_fast(m1s);
                float w2 = softplus_fast(m2s);
                float w3 = softplus_fast(m3s);
                float sb0 = b0[c * 3 + 0] + b0[c * 3 + 1] + b0[c * 3 + 2];
                float s1  = b1[c * 3 + 0] + b1[c * 3 + 1] + b1[c * 3 + 2] + 3.f * w1 * sb0;
                float s2  = b2[c * 3 + 0] + b2[c * 3 + 1] + b2[c * 3 + 2] + 3.f * w2 * s1;
                float A = 27.f * w0 * w1 * w2 * w3;
                float B = b3[c] + w3 * s2;
                ((float*)s_A4)[c]  = A;
                ((float*)s_Bu4)[c] = B + 0.5f * A;
            }
        } else if (t < C_CH) {
            // ---- per-channel compose (rare: non-uniform m, zero gates) ----
            int c = t;
            float a0[3], bb[3];
            #pragma unroll
            for (int jj = 0; jj < 3; jj++) {
                a0[jj] = softplus_fast(m0[c * 3 + jj]);
                bb[jj] = b0[c * 3 + jj];
            }
            float a1[3], bv1[3];
            #pragma unroll
            for (int ii = 0; ii < 3; ii++) {
                float sp, av = 0.f, bv = b1[c * 3 + ii];
                #pragma unroll
                for (int jj = 0; jj < 3; jj++) {
                    sp = softplus_fast(m1[c * 9 + ii * 3 + jj]);
                    av = fmaf(sp, a0[jj], av);
                    bv = fmaf(sp, bb[jj], bv);
                }
                a1[ii] = av; bv1[ii] = bv;
            }
            float a2[3], bv2[3];
            #pragma unroll
            for (int ii = 0; ii < 3; ii++) {
                float sp, av = 0.f, bv = b2[c * 3 + ii];
                #pragma unroll
                for (int jj = 0; jj < 3; jj++) {
                    sp = softplus_fast(m2[c * 9 + ii * 3 + jj]);
                    av = fmaf(sp, a1[jj], av);
                    bv = fmaf(sp, bv1[jj], bv);
                }
                a2[ii] = av; bv2[ii] = bv;
            }
            float A = 0.f, B = b3[c];
            #pragma unroll
            for (int jj = 0; jj < 3; jj++) {
                float sp = softplus_fast(m3[c * 3 + jj]);
                A = fmaf(sp, a2[jj], A);
                B = fmaf(sp, bv2[jj], B);
            }
            ((float*)s_A4)[c]  = A;
            ((float*)s_Bu4)[c] = B + 0.5f * A;
        }
        __syncthreads();

        // ---- streaming section: identical to the proven hot loop ----
        float4 A  = s_A4[cg];
        float4 Bu = s_Bu4[cg];

        float4 xa = in[i];
        float4 na = noise[i];
        float4 xb = in[j];
        float4 nb = noise[j];
        xa.x += na.x; xa.y += na.y; xa.z += na.z; xa.w += na.w;
        xb.x += nb.x; xb.y += nb.y; xb.z += nb.z; xb.w += nb.w;
        if (write_outputs) { out_o[i] = xa; out_o[j] = xb; }

        float ua_x = fmaf(A.x, xa.x, Bu.x);
        float ua_y = fmaf(A.y, xa.y, Bu.y);
        float ua_z = fmaf(A.z, xa.z, Bu.z);
        float ua_w = fmaf(A.w, xa.w, Bu.w);
        float ub_x = fmaf(A.x, xb.x, Bu.x);
        float ub_y = fmaf(A.y, xb.y, Bu.y);
        float ub_z = fmaf(A.z, xb.z, Bu.z);
        float ub_w = fmaf(A.w, xb.w, Bu.w);

        float4 la, lb;
        la.x = sig_diff_clamp(ua_x, ua_x - A.x);
        la.y = sig_diff_clamp(ua_y, ua_y - A.y);
        la.z = sig_diff_clamp(ua_z, ua_z - A.z);
        la.w = sig_diff_clamp(ua_w, ua_w - A.w);
        lb.x = sig_diff_clamp(ub_x, ub_x - A.x);
        lb.y = sig_diff_clamp(ub_y, ub_y - A.y);
        lb.z = sig_diff_clamp(ub_z, ub_z - A.z);
        lb.w = sig_diff_clamp(ub_w, ub_w - A.w);

        out_l[i] = la;
        out_l[j] = lb;
    } else {
        // ---- general path (rare): params to shared, gated chain, spills OK --
        for (int idx = t; idx < 1536; idx += 256) {
            if (idx < 192)        s_sp0[idx]        = log1pf(expf(m0[idx]));
            else if (idx < 768)   s_sp1[idx - 192]  = log1pf(expf(m1[idx - 192]));
            else if (idx < 1344)  s_sp2[idx - 768]  = log1pf(expf(m2[idx - 768]));
            else                  s_sp3[idx - 1344] = log1pf(expf(m3[idx - 1344]));
        }
        for (int idx = t; idx < 640; idx += 256) {
            if (idx < 192)       s_tf0[idx]       = tanhf(f0[idx]);
            else if (idx < 384)  s_tf1[idx - 192] = tanhf(f1[idx - 192]);
            else if (idx < 576)  s_tf2[idx - 384] = tanhf(f2[idx - 384]);
            else                 s_tf3[idx - 576] = tanhf(f3[idx - 576]);
        }
        for (int idx = t; idx < 192; idx += 256) {
            s_b0[idx] = b0[idx];
            s_b1[idx] = b1[idx];
            s_b2[idx] = b2[idx];
        }
        if (t < 64) s_b3[t] = b3[t];
        __syncthreads();

        int c0 = cg * 4;
        #pragma unroll
        for (int half = 0; half < 2; half++) {
            int idx = half ? j : i;
            float4 x4 = in[idx];
            float4 n4 = noise[idx];
            x4.x += n4.x; x4.y += n4.y; x4.z += n4.z; x4.w += n4.w;
            if (write_outputs) out_o[idx] = x4;

            float vx[4] = {x4.x, x4.y, x4.z, x4.w};
            float lo[4];
            #pragma unroll
            for (int k = 0; k < 4; k++) {
                float u = chain_shared(vx[k] + 0.5f, c0 + k,
                                       s_sp0, s_b0, s_tf0, s_sp1, s_b1, s_tf1,
                                       s_sp2, s_b2, s_tf2, s_sp3, s_b3, s_tf3);
                float l = chain_shared(vx[k] - 0.5f, c0 + k,
                                       s_sp0, s_b0, s_tf0, s_sp1, s_b1, s_tf1,
                                       s_sp2, s_b2, s_tf2, s_sp3, s_b3, s_tf3);
                lo[k] = sig_diff_clamp(u, l);
            }
            float4 lk;
            lk.x = lo[0]; lk.y = lo[1]; lk.z = lo[2]; lk.w = lo[3];
            out_l[idx] = lk;
        }
    }
}

// ---------------- launch ----------------
extern "C" void kernel_launch(void* const* d_in, const int* in_sizes, int n_in,
                              void* d_out, int out_size)
{
    const float* inputs = (const float*)d_in[0];
    const float* noise  = (const float*)d_in[1];
    const float* m0 = (const float*)d_in[2];
    const float* b0 = (const float*)d_in[3];
    const float* f0 = (const float*)d_in[4];
    const float* m1 = (const float*)d_in[5];
    const float* b1 = (const float*)d_in[6];
    const float* f1 = (const float*)d_in[7];
    const float* m2 = (const float*)d_in[8];
    const float* b2 = (const float*)d_in[9];
    const float* f2 = (const float*)d_in[10];
    const float* m3 = (const float*)d_in[11];
    const float* b3 = (const float*)d_in[12];
    const float* f3 = (const float*)d_in[13];

    float* out = (float*)d_out;
    float* out_outputs;
    float* out_lik;
    int write_outputs;
    if (out_size >= 2 * NC) {
        out_outputs = out;          // (N, C) outputs first
        out_lik     = out + NC;     // then (N, C) likelihood
        write_outputs = 1;
    } else {
        out_outputs = out;
        out_lik     = out;
        write_outputs = 0;
    }

    eb_all<<<NC8 / 256, 256>>>((const float4*)inputs, (const float4*)noise,
                               (float4*)out_outputs, (float4*)out_lik, write_outputs,
                               m0, b0, f0, m1, b1, f1, m2, b2, f2, m3, b3, f3);
}